// round 10
// baseline (speedup 1.0000x reference)
#include <cuda_runtime.h>
#include <cstdint>

// PlaneModel: B=8192, NS=32, P=64, HID1=16, BASE=32, OUT=13, D_IN=79
// Layer-1 GEMV on mma.sync tf32 (3xTF32 split). warp = batch: 32 rows x 16 ch x K80.
// A staged in a 32-col warp-private buffer, consumed in 3 phases (xz lo, xz hi, pose).
#define FULL 0xffffffffu
#define ZS 36        // 32 cols + 4 pad: frag reads (4*gr+j+c) mod 32 all-distinct -> conflict-free
#define BSTR 24      // B table stride: conflict-free frag reads

__device__ __forceinline__ uint32_t f2tf(float x){
    uint32_t r; asm("cvt.rna.tf32.f32 %0, %1;" : "=r"(r) : "f"(x)); return r;
}
__device__ __forceinline__ void mma8(float* d, const uint32_t* a, const uint32_t* b){
    asm volatile("mma.sync.aligned.m16n8k8.row.col.f32.tf32.tf32.f32 "
        "{%0,%1,%2,%3},{%4,%5,%6,%7},{%8,%9},{%0,%1,%2,%3};"
        : "+f"(d[0]), "+f"(d[1]), "+f"(d[2]), "+f"(d[3])
        : "r"(a[0]), "r"(a[1]), "r"(a[2]), "r"(a[3]), "r"(b[0]), "r"(b[1]));
}
__device__ __forceinline__ float wsum(float x){
    x += __shfl_xor_sync(FULL, x, 16);
    x += __shfl_xor_sync(FULL, x, 8);
    x += __shfl_xor_sync(FULL, x, 4);
    x += __shfl_xor_sync(FULL, x, 2);
    x += __shfl_xor_sync(FULL, x, 1);
    return x;
}

// one K8 chunk: kAg = global k (with j folded in), lcol = column in the warp buffer
__device__ __forceinline__ void do_chunk(float d[2][2][4], const float* szw,
                                         const float* s_bh, const float* s_bl,
                                         int kAg, int lcol, int gr){
    uint32_t bh[2][2], bl[2][2];
    #pragma unroll
    for (int nt = 0; nt < 2; nt++){
        bh[nt][0] = __float_as_uint(s_bh[(kAg  )*BSTR + nt*8 + gr]);
        bh[nt][1] = __float_as_uint(s_bh[(kAg+4)*BSTR + nt*8 + gr]);
        bl[nt][0] = __float_as_uint(s_bl[(kAg  )*BSTR + nt*8 + gr]);
        bl[nt][1] = __float_as_uint(s_bl[(kAg+4)*BSTR + nt*8 + gr]);
    }
    #pragma unroll
    for (int mt = 0; mt < 2; mt++){
        const float* base = szw + (mt*16 + gr)*ZS + lcol;
        float a0 = base[0];
        float a1 = base[8*ZS];
        float a2 = base[4];
        float a3 = base[8*ZS + 4];
        uint32_t ah[4] = { f2tf(a0), f2tf(a1), f2tf(a2), f2tf(a3) };
        uint32_t al[4] = { f2tf(a0 - __uint_as_float(ah[0])),
                           f2tf(a1 - __uint_as_float(ah[1])),
                           f2tf(a2 - __uint_as_float(ah[2])),
                           f2tf(a3 - __uint_as_float(ah[3])) };
        #pragma unroll
        for (int nt = 0; nt < 2; nt++){
            mma8(d[mt][nt], ah, bh[nt]);
            mma8(d[mt][nt], al, bh[nt]);
            mma8(d[mt][nt], ah, bl[nt]);
        }
    }
}

__global__ void __launch_bounds__(256, 4)
plane_kernel(const float* __restrict__ g_pos,  const float* __restrict__ g_quat,
             const float* __restrict__ g_xz,   const float* __restrict__ g_aabb,
             const int*   __restrict__ g_widx, const float* __restrict__ g_pls,
             const float* __restrict__ g_w1,   const float* __restrict__ g_b1,
             const float* __restrict__ g_g1,   const float* __restrict__ g_be1,
             const float* __restrict__ g_w2a,  const float* __restrict__ g_b2a,
             const float* __restrict__ g_g2a,  const float* __restrict__ g_be2a,
             const float* __restrict__ g_w2b,  const float* __restrict__ g_b2b,
             const float* __restrict__ g_g2b,  const float* __restrict__ g_be2b,
             const float* __restrict__ g_wout, const float* __restrict__ g_bout,
             float* __restrict__ g_out)
{
    extern __shared__ __align__(16) float smem[];
    float* s_bh = smem;                 // 80*24 tf32(hi) weights [k][n]
    float* s_bl = s_bh + 80*BSTR;       // 80*24 tf32(lo)
    float* s_v  = s_bl + 80*BSTR;       // 8*16 per-warp layer-1 sums
    float* s_z  = s_v + 128;            // 8 * 32*ZS  A staging (one 32-col phase buffer/warp)

    const int tid  = threadIdx.x;
    const int warp = tid >> 5, lane = tid & 31;
    const int j    = lane & 3;          // thread in quad
    const int gr   = lane >> 2;         // group 0..7
    const int b    = (blockIdx.x << 3) + warp;
    float* szw = s_z + warp*(32*ZS);

    // ---- W hi/lo tf32 tables (feature-permuted: xz 0..63, pick 64..66, pose 67..78, 79=0)
    for (int e = tid; e < 1280; e += 256){
        int k = e >> 4, n = e & 15;
        float w = 0.f;
        if (k < 79){
            int f = (k < 64) ? k + 3 : ((k < 67) ? k - 64 : k);
            w = __ldg(g_w1 + f*16 + n);
        }
        uint32_t hi = f2tf(w);
        float lo = w - __uint_as_float(hi);
        s_bh[k*BSTR + n] = __uint_as_float(hi);
        s_bl[k*BSTR + n] = __uint_as_float(f2tf(lo));
    }

    const int idx = __ldg(g_widx + b*32 + lane);
    const float* xzb = g_xz + ((size_t)b << 15);

    // ---- phase A staging: xz cols 0..31 ----
    #pragma unroll
    for (int r = 0; r < 32; r++){
        int ir = __shfl_sync(FULL, idx, r);
        szw[r*ZS + lane] = __ldcs(xzb + (ir << 6) + lane);
    }

    // ---- pose features (registers; overlap staging latency) ----
    float p[16];
    {
        float qx = __ldg(g_quat + b*4 + 0), qy = __ldg(g_quat + b*4 + 1);
        float qz = __ldg(g_quat + b*4 + 2), qw = __ldg(g_quat + b*4 + 3);
        float rn = rsqrtf(qx*qx + qy*qy + qz*qz + qw*qw);
        qx *= rn; qy *= rn; qz *= rn; qw *= rn;
        float r00 = 1.f - 2.f*(qy*qy + qz*qz), r01 = 2.f*(qx*qy - qz*qw), r02 = 2.f*(qx*qz + qy*qw);
        float r10 = 2.f*(qx*qy + qz*qw), r11 = 1.f - 2.f*(qx*qx + qz*qz), r12 = 2.f*(qy*qz - qx*qw);
        float r20 = 2.f*(qx*qz - qy*qw), r21 = 2.f*(qy*qz + qx*qw), r22 = 1.f - 2.f*(qx*qx + qy*qy);
        float px = __ldg(g_pos + b*3 + 0), py = __ldg(g_pos + b*3 + 1), pz = __ldg(g_pos + b*3 + 2);
        float lox = __ldg(g_aabb + b*6 + 0), loy = __ldg(g_aabb + b*6 + 1), loz = __ldg(g_aabb + b*6 + 2);
        float hix = __ldg(g_aabb + b*6 + 3), hiy = __ldg(g_aabb + b*6 + 4), hiz = __ldg(g_aabb + b*6 + 5);
        float ci = (float)(idx >> 6) + 0.5f, cj = (float)((idx >> 3) & 7) + 0.5f, ck = (float)(idx & 7) + 0.5f;
        float vx = (ci*0.125f)*(hix - lox) + lox;
        float vy = (cj*0.125f)*(hiy - loy) + loy;
        float vz = (ck*0.125f)*(hiz - loz) + loz;
        float e = __expf(__ldg(g_pls));
        p[0] = r00*vx + r01*vy + r02*vz + px;
        p[1] = r10*vx + r11*vy + r12*vz + py;
        p[2] = r20*vx + r21*vy + r22*vz + pz;
        p[3] = px*e; p[4] = py*e; p[5] = pz*e;
        p[6] = r00; p[7] = r01; p[8] = r02;
        p[9] = r10; p[10] = r11; p[11] = r12;
        p[12] = r20; p[13] = r21; p[14] = r22;
        p[15] = 0.f;
    }
    __syncthreads();    // W tables + phase A visible

    float d[2][2][4];
    #pragma unroll
    for (int mt = 0; mt < 2; mt++)
        #pragma unroll
        for (int nt = 0; nt < 2; nt++)
            #pragma unroll
            for (int q = 0; q < 4; q++) d[mt][nt][q] = 0.f;

    // ---- consume phase A: k-chunks 0..3 ----
    #pragma unroll
    for (int k0 = 0; k0 < 4; k0++)
        do_chunk(d, szw, s_bh, s_bl, k0*8 + j, k0*8 + j, gr);
    __syncwarp(FULL);

    // ---- phase B staging: xz cols 32..63 ----
    #pragma unroll
    for (int r = 0; r < 32; r++){
        int ir = __shfl_sync(FULL, idx, r);
        szw[r*ZS + lane] = __ldcs(xzb + (ir << 6) + 32 + lane);
    }
    __syncwarp(FULL);

    // ---- consume phase B: k-chunks 4..7 ----
    #pragma unroll
    for (int k0 = 4; k0 < 8; k0++)
        do_chunk(d, szw, s_bh, s_bl, k0*8 + j, k0*8 + j - 32, gr);
    __syncwarp(FULL);

    // ---- phase C staging: pose -> buffer cols 0..15 (row = lane) ----
    #pragma unroll
    for (int t = 0; t < 4; t++)
        *(float4*)(szw + lane*ZS + 4*t) = make_float4(p[4*t], p[4*t+1], p[4*t+2], p[4*t+3]);
    __syncwarp(FULL);

    // ---- consume phase C: k-chunks 8..9 ----
    #pragma unroll
    for (int k0 = 8; k0 < 10; k0++)
        do_chunk(d, szw, s_bh, s_bl, k0*8 + j, k0*8 + j - 64, gr);

    // ---- epilogue: bias + relu + LN(16) per sample (quad shfl), x2, sum over samples ----
    float b1v[4] = { __ldg(g_b1 + 2*j),  __ldg(g_b1 + 2*j + 1),
                     __ldg(g_b1 + 8 + 2*j), __ldg(g_b1 + 9 + 2*j) };
    float g1v[4] = { __ldg(g_g1 + 2*j),  __ldg(g_g1 + 2*j + 1),
                     __ldg(g_g1 + 8 + 2*j), __ldg(g_g1 + 9 + 2*j) };
    float be1v[4] = { __ldg(g_be1 + 2*j), __ldg(g_be1 + 2*j + 1),
                      __ldg(g_be1 + 8 + 2*j), __ldg(g_be1 + 9 + 2*j) };

    float vsum[4] = {0.f, 0.f, 0.f, 0.f};
    #pragma unroll
    for (int mt = 0; mt < 2; mt++){
        #pragma unroll
        for (int rl = 0; rl < 2; rl++){
            float y0 = fmaxf(d[mt][0][rl*2]   + b1v[0], 0.f);
            float y1 = fmaxf(d[mt][0][rl*2+1] + b1v[1], 0.f);
            float y2 = fmaxf(d[mt][1][rl*2]   + b1v[2], 0.f);
            float y3 = fmaxf(d[mt][1][rl*2+1] + b1v[3], 0.f);
            float s = (y0 + y1) + (y2 + y3);
            s += __shfl_xor_sync(FULL, s, 1);
            s += __shfl_xor_sync(FULL, s, 2);
            float m = s * 0.0625f;
            float q0 = y0 - m, q1 = y1 - m, q2 = y2 - m, q3 = y3 - m;
            float q = (q0*q0 + q1*q1) + (q2*q2 + q3*q3);
            q += __shfl_xor_sync(FULL, q, 1);
            q += __shfl_xor_sync(FULL, q, 2);
            float is2 = 2.f * rsqrtf(q * 0.0625f + 1e-6f);   // LN then z+z
            vsum[0] += q0 * is2 * g1v[0] + 2.f*be1v[0];
            vsum[1] += q1 * is2 * g1v[1] + 2.f*be1v[1];
            vsum[2] += q2 * is2 * g1v[2] + 2.f*be1v[2];
            vsum[3] += q3 * is2 * g1v[3] + 2.f*be1v[3];
        }
    }
    #pragma unroll
    for (int c = 0; c < 4; c++){
        vsum[c] += __shfl_xor_sync(FULL, vsum[c], 4);
        vsum[c] += __shfl_xor_sync(FULL, vsum[c], 8);
        vsum[c] += __shfl_xor_sync(FULL, vsum[c], 16);
    }
    if (gr == 0){
        float* sv = s_v + warp*16;
        sv[2*j]     = vsum[0];
        sv[2*j + 1] = vsum[1];
        sv[8 + 2*j] = vsum[2];
        sv[9 + 2*j] = vsum[3];
    }
    __syncwarp(FULL);
    float v[16];
    #pragma unroll
    for (int t = 0; t < 4; t++){
        float4 s4 = *(const float4*)(s_v + warp*16 + 4*t);
        v[4*t] = s4.x; v[4*t+1] = s4.y; v[4*t+2] = s4.z; v[4*t+3] = s4.w;
    }

    // ---- head: lane = channel ----
    {
        float a0 = __ldg(g_b2a + lane), a1 = 0.f, a2 = 0.f, a3 = 0.f;
        #pragma unroll
        for (int i = 0; i < 16; i += 4){
            a0 = fmaf(v[i+0], __ldg(g_w2a + (i+0)*32 + lane), a0);
            a1 = fmaf(v[i+1], __ldg(g_w2a + (i+1)*32 + lane), a1);
            a2 = fmaf(v[i+2], __ldg(g_w2a + (i+2)*32 + lane), a2);
            a3 = fmaf(v[i+3], __ldg(g_w2a + (i+3)*32 + lane), a3);
        }
        float a = (a0 + a1) + (a2 + a3);
        a = fmaxf(a, 0.f);
        float ma = wsum(a) * 0.03125f;
        float da = a - ma;
        float va = wsum(da*da) * 0.03125f;
        float ya = da * rsqrtf(va + 1e-6f) * __ldg(g_g2a + lane) + __ldg(g_be2a + lane);

        float c0 = __ldg(g_b2b + lane), c1 = 0.f, c2 = 0.f, c3 = 0.f;
        #pragma unroll
        for (int i = 0; i < 32; i += 4){
            c0 = fmaf(__shfl_sync(FULL, ya, i+0), __ldg(g_w2b + (i+0)*32 + lane), c0);
            c1 = fmaf(__shfl_sync(FULL, ya, i+1), __ldg(g_w2b + (i+1)*32 + lane), c1);
            c2 = fmaf(__shfl_sync(FULL, ya, i+2), __ldg(g_w2b + (i+2)*32 + lane), c2);
            c3 = fmaf(__shfl_sync(FULL, ya, i+3), __ldg(g_w2b + (i+3)*32 + lane), c3);
        }
        float c = (c0 + c1) + (c2 + c3);
        c = fmaxf(c, 0.f);
        float mc = wsum(c) * 0.03125f;
        float dc = c - mc;
        float vc = wsum(dc*dc) * 0.03125f;
        float yb = dc * rsqrtf(vc + 1e-6f) * __ldg(g_g2b + lane) + __ldg(g_be2b + lane);
        float zf = yb + ya;   // residual

        float o0 = (lane < 13) ? __ldg(g_bout + lane) : 0.f;
        float o1 = 0.f;
        #pragma unroll
        for (int i = 0; i < 32; i += 2){
            float zi0 = __shfl_sync(FULL, zf, i);
            float zi1 = __shfl_sync(FULL, zf, i+1);
            if (lane < 13){
                o0 = fmaf(zi0, __ldg(g_wout + (i  )*13 + lane), o0);
                o1 = fmaf(zi1, __ldg(g_wout + (i+1)*13 + lane), o1);
            }
        }
        if (lane < 13) g_out[b*13 + lane] = tanhf(o0 + o1);
    }
}

extern "C" void kernel_launch(void* const* d_in, const int* in_sizes, int n_in,
                              void* d_out, int out_size)
{
    (void)in_sizes; (void)n_in; (void)out_size;
    const int SMEM_BYTES = (80*BSTR*2 + 128 + 8*32*ZS) * 4;   // ~52.8 KB -> 4 blocks/SM
    cudaFuncSetAttribute(plane_kernel,
                         cudaFuncAttributeMaxDynamicSharedMemorySize, SMEM_BYTES);
    plane_kernel<<<1024, 256, SMEM_BYTES>>>(
        (const float*)d_in[0],  (const float*)d_in[1],  (const float*)d_in[2],
        (const float*)d_in[3],  (const int*)  d_in[4],  (const float*)d_in[5],
        (const float*)d_in[6],  (const float*)d_in[7],  (const float*)d_in[8],
        (const float*)d_in[9],  (const float*)d_in[10], (const float*)d_in[11],
        (const float*)d_in[12], (const float*)d_in[13], (const float*)d_in[14],
        (const float*)d_in[15], (const float*)d_in[16], (const float*)d_in[17],
        (const float*)d_in[18], (const float*)d_in[19],
        (float*)d_out);
}

// round 11
// speedup vs baseline: 1.4638x; 1.4638x over previous
#include <cuda_runtime.h>
#include <cstdint>

// PlaneModel: B=8192, NS=32, P=64, HID1=16, BASE=32, OUT=13, D_IN=79
// Layer-1 GEMV on mma.sync tf32 (3xTF32 split, 3 independent accumulator sets).
// warp = batch: 32 rows x 16 ch x K80, A staged once (all 80 cols), ZS=84.
#define FULL 0xffffffffu
#define ZS 84        // frag reads (20*gr + j + c) mod 32 all-distinct -> conflict-free
#define BSTR 24      // B table stride: conflict-free frag reads

__device__ __forceinline__ uint32_t f2tf(float x){
    uint32_t r; asm("cvt.rna.tf32.f32 %0, %1;" : "=r"(r) : "f"(x)); return r;
}
__device__ __forceinline__ void mma8(float* d, const uint32_t* a, const uint32_t* b){
    asm volatile("mma.sync.aligned.m16n8k8.row.col.f32.tf32.tf32.f32 "
        "{%0,%1,%2,%3},{%4,%5,%6,%7},{%8,%9},{%0,%1,%2,%3};"
        : "+f"(d[0]), "+f"(d[1]), "+f"(d[2]), "+f"(d[3])
        : "r"(a[0]), "r"(a[1]), "r"(a[2]), "r"(a[3]), "r"(b[0]), "r"(b[1]));
}
__device__ __forceinline__ float wsum(float x){
    x += __shfl_xor_sync(FULL, x, 16);
    x += __shfl_xor_sync(FULL, x, 8);
    x += __shfl_xor_sync(FULL, x, 4);
    x += __shfl_xor_sync(FULL, x, 2);
    x += __shfl_xor_sync(FULL, x, 1);
    return x;
}

__global__ void __launch_bounds__(256)
plane_kernel(const float* __restrict__ g_pos,  const float* __restrict__ g_quat,
             const float* __restrict__ g_xz,   const float* __restrict__ g_aabb,
             const int*   __restrict__ g_widx, const float* __restrict__ g_pls,
             const float* __restrict__ g_w1,   const float* __restrict__ g_b1,
             const float* __restrict__ g_g1,   const float* __restrict__ g_be1,
             const float* __restrict__ g_w2a,  const float* __restrict__ g_b2a,
             const float* __restrict__ g_g2a,  const float* __restrict__ g_be2a,
             const float* __restrict__ g_w2b,  const float* __restrict__ g_b2b,
             const float* __restrict__ g_g2b,  const float* __restrict__ g_be2b,
             const float* __restrict__ g_wout, const float* __restrict__ g_bout,
             float* __restrict__ g_out)
{
    extern __shared__ __align__(16) float smem[];
    float* s_bh = smem;                 // 80*24 tf32(hi) weights [k][n]
    float* s_bl = s_bh + 80*BSTR;       // 80*24 tf32(lo)
    float* s_v  = s_bl + 80*BSTR;       // 8*16 per-warp layer-1 sums
    float* s_z  = s_v + 128;            // 8 * 32*ZS A staging

    const int tid  = threadIdx.x;
    const int warp = tid >> 5, lane = tid & 31;
    const int j    = lane & 3;          // thread in quad
    const int gr   = lane >> 2;         // group 0..7
    const int b    = (blockIdx.x << 3) + warp;
    float* szw = s_z + warp*(32*ZS);

    // ---- W hi/lo tf32 tables (feature-permuted: xz 0..63, pick 64..66, pose 67..78, 79=0)
    for (int e = tid; e < 1280; e += 256){
        int k = e >> 4, n = e & 15;
        float w = 0.f;
        if (k < 79){
            int f = (k < 64) ? k + 3 : ((k < 67) ? k - 64 : k);
            w = __ldg(g_w1 + f*16 + n);
        }
        uint32_t hi = f2tf(w);
        float lo = w - __uint_as_float(hi);
        s_bh[k*BSTR + n] = __uint_as_float(hi);
        s_bl[k*BSTR + n] = __uint_as_float(f2tf(lo));
    }

    // ---- stage A: xz gather to cols 0..63 (coalesced LDG.32, conflict-free STS)
    const int idx = __ldg(g_widx + b*32 + lane);
    const float* xzb = g_xz + ((size_t)b << 15);
    #pragma unroll
    for (int r = 0; r < 32; r++){
        int ir = __shfl_sync(FULL, idx, r);
        const float* src = xzb + (ir << 6);
        szw[r*ZS + lane]      = __ldcs(src + lane);
        szw[r*ZS + 32 + lane] = __ldcs(src + 32 + lane);
    }

    // ---- pose features for this lane's sample -> cols 64..79 (row = lane)
    {
        float qx = __ldg(g_quat + b*4 + 0), qy = __ldg(g_quat + b*4 + 1);
        float qz = __ldg(g_quat + b*4 + 2), qw = __ldg(g_quat + b*4 + 3);
        float rn = rsqrtf(qx*qx + qy*qy + qz*qz + qw*qw);
        qx *= rn; qy *= rn; qz *= rn; qw *= rn;
        float r00 = 1.f - 2.f*(qy*qy + qz*qz), r01 = 2.f*(qx*qy - qz*qw), r02 = 2.f*(qx*qz + qy*qw);
        float r10 = 2.f*(qx*qy + qz*qw), r11 = 1.f - 2.f*(qx*qx + qz*qz), r12 = 2.f*(qy*qz - qx*qw);
        float r20 = 2.f*(qx*qz - qy*qw), r21 = 2.f*(qy*qz + qx*qw), r22 = 1.f - 2.f*(qx*qx + qy*qy);
        float px = __ldg(g_pos + b*3 + 0), py = __ldg(g_pos + b*3 + 1), pz = __ldg(g_pos + b*3 + 2);
        float lox = __ldg(g_aabb + b*6 + 0), loy = __ldg(g_aabb + b*6 + 1), loz = __ldg(g_aabb + b*6 + 2);
        float hix = __ldg(g_aabb + b*6 + 3), hiy = __ldg(g_aabb + b*6 + 4), hiz = __ldg(g_aabb + b*6 + 5);
        float ci = (float)(idx >> 6) + 0.5f, cj = (float)((idx >> 3) & 7) + 0.5f, ck = (float)(idx & 7) + 0.5f;
        float vx = (ci*0.125f)*(hix - lox) + lox;
        float vy = (cj*0.125f)*(hiy - loy) + loy;
        float vz = (ck*0.125f)*(hiz - loz) + loz;
        float e = __expf(__ldg(g_pls));
        float* prow = szw + lane*ZS;
        prow[64] = r00*vx + r01*vy + r02*vz + px;
        prow[65] = r10*vx + r11*vy + r12*vz + py;
        prow[66] = r20*vx + r21*vy + r22*vz + pz;
        prow[67] = px*e; prow[68] = py*e; prow[69] = pz*e;
        prow[70] = r00; prow[71] = r01; prow[72] = r02;
        prow[73] = r10; prow[74] = r11; prow[75] = r12;
        prow[76] = r20; prow[77] = r21; prow[78] = r22;
        prow[79] = 0.f;
    }
    __syncthreads();

    // ---- 3xTF32 MMA, 3 independent accumulator sets (12 chains of depth 10)
    float dA[2][2][4], dB[2][2][4], dC[2][2][4];
    #pragma unroll
    for (int mt = 0; mt < 2; mt++)
        #pragma unroll
        for (int nt = 0; nt < 2; nt++)
            #pragma unroll
            for (int q = 0; q < 4; q++){ dA[mt][nt][q] = 0.f; dB[mt][nt][q] = 0.f; dC[mt][nt][q] = 0.f; }

    #pragma unroll
    for (int k0 = 0; k0 < 10; k0++){
        const int kA = k0*8 + j;
        uint32_t bh[2][2], bl[2][2];
        #pragma unroll
        for (int nt = 0; nt < 2; nt++){
            bh[nt][0] = __float_as_uint(s_bh[(kA  )*BSTR + nt*8 + gr]);
            bh[nt][1] = __float_as_uint(s_bh[(kA+4)*BSTR + nt*8 + gr]);
            bl[nt][0] = __float_as_uint(s_bl[(kA  )*BSTR + nt*8 + gr]);
            bl[nt][1] = __float_as_uint(s_bl[(kA+4)*BSTR + nt*8 + gr]);
        }
        #pragma unroll
        for (int mt = 0; mt < 2; mt++){
            const float* base = szw + (mt*16 + gr)*ZS + kA;
            float a0 = base[0];
            float a1 = base[8*ZS];
            float a2 = base[4];
            float a3 = base[8*ZS + 4];
            uint32_t ah[4] = { f2tf(a0), f2tf(a1), f2tf(a2), f2tf(a3) };
            uint32_t al[4] = { f2tf(a0 - __uint_as_float(ah[0])),
                               f2tf(a1 - __uint_as_float(ah[1])),
                               f2tf(a2 - __uint_as_float(ah[2])),
                               f2tf(a3 - __uint_as_float(ah[3])) };
            #pragma unroll
            for (int nt = 0; nt < 2; nt++){
                mma8(dA[mt][nt], ah, bh[nt]);
                mma8(dB[mt][nt], al, bh[nt]);
                mma8(dC[mt][nt], ah, bl[nt]);
            }
        }
    }

    // combine the 3 sets
    float d[2][2][4];
    #pragma unroll
    for (int mt = 0; mt < 2; mt++)
        #pragma unroll
        for (int nt = 0; nt < 2; nt++)
            #pragma unroll
            for (int q = 0; q < 4; q++)
                d[mt][nt][q] = dA[mt][nt][q] + (dB[mt][nt][q] + dC[mt][nt][q]);

    // ---- epilogue: bias + relu + LN(16) per sample (quad shfl), x2, sum over samples ----
    float b1v[4] = { __ldg(g_b1 + 2*j),  __ldg(g_b1 + 2*j + 1),
                     __ldg(g_b1 + 8 + 2*j), __ldg(g_b1 + 9 + 2*j) };
    float g1v[4] = { __ldg(g_g1 + 2*j),  __ldg(g_g1 + 2*j + 1),
                     __ldg(g_g1 + 8 + 2*j), __ldg(g_g1 + 9 + 2*j) };
    float be1v[4] = { __ldg(g_be1 + 2*j), __ldg(g_be1 + 2*j + 1),
                      __ldg(g_be1 + 8 + 2*j), __ldg(g_be1 + 9 + 2*j) };

    float vsum[4] = {0.f, 0.f, 0.f, 0.f};
    #pragma unroll
    for (int mt = 0; mt < 2; mt++){
        #pragma unroll
        for (int rl = 0; rl < 2; rl++){
            float y0 = fmaxf(d[mt][0][rl*2]   + b1v[0], 0.f);
            float y1 = fmaxf(d[mt][0][rl*2+1] + b1v[1], 0.f);
            float y2 = fmaxf(d[mt][1][rl*2]   + b1v[2], 0.f);
            float y3 = fmaxf(d[mt][1][rl*2+1] + b1v[3], 0.f);
            float s = (y0 + y1) + (y2 + y3);
            s += __shfl_xor_sync(FULL, s, 1);
            s += __shfl_xor_sync(FULL, s, 2);
            float m = s * 0.0625f;
            float q0 = y0 - m, q1 = y1 - m, q2 = y2 - m, q3 = y3 - m;
            float q = (q0*q0 + q1*q1) + (q2*q2 + q3*q3);
            q += __shfl_xor_sync(FULL, q, 1);
            q += __shfl_xor_sync(FULL, q, 2);
            float is2 = 2.f * rsqrtf(q * 0.0625f + 1e-6f);   // LN then z+z
            vsum[0] += q0 * is2 * g1v[0] + 2.f*be1v[0];
            vsum[1] += q1 * is2 * g1v[1] + 2.f*be1v[1];
            vsum[2] += q2 * is2 * g1v[2] + 2.f*be1v[2];
            vsum[3] += q3 * is2 * g1v[3] + 2.f*be1v[3];
        }
    }
    #pragma unroll
    for (int c = 0; c < 4; c++){
        vsum[c] += __shfl_xor_sync(FULL, vsum[c], 4);
        vsum[c] += __shfl_xor_sync(FULL, vsum[c], 8);
        vsum[c] += __shfl_xor_sync(FULL, vsum[c], 16);
    }
    if (gr == 0){
        float* sv = s_v + warp*16;
        sv[2*j]     = vsum[0];
        sv[2*j + 1] = vsum[1];
        sv[8 + 2*j] = vsum[2];
        sv[9 + 2*j] = vsum[3];
    }
    __syncwarp(FULL);
    float v[16];
    #pragma unroll
    for (int t = 0; t < 4; t++){
        float4 s4 = *(const float4*)(s_v + warp*16 + 4*t);
        v[4*t] = s4.x; v[4*t+1] = s4.y; v[4*t+2] = s4.z; v[4*t+3] = s4.w;
    }

    // ---- head: lane = channel ----
    {
        float a0 = __ldg(g_b2a + lane), a1 = 0.f, a2 = 0.f, a3 = 0.f;
        #pragma unroll
        for (int i = 0; i < 16; i += 4){
            a0 = fmaf(v[i+0], __ldg(g_w2a + (i+0)*32 + lane), a0);
            a1 = fmaf(v[i+1], __ldg(g_w2a + (i+1)*32 + lane), a1);
            a2 = fmaf(v[i+2], __ldg(g_w2a + (i+2)*32 + lane), a2);
            a3 = fmaf(v[i+3], __ldg(g_w2a + (i+3)*32 + lane), a3);
        }
        float a = (a0 + a1) + (a2 + a3);
        a = fmaxf(a, 0.f);
        float ma = wsum(a) * 0.03125f;
        float da = a - ma;
        float va = wsum(da*da) * 0.03125f;
        float ya = da * rsqrtf(va + 1e-6f) * __ldg(g_g2a + lane) + __ldg(g_be2a + lane);

        float c0 = __ldg(g_b2b + lane), c1 = 0.f, c2 = 0.f, c3 = 0.f;
        #pragma unroll
        for (int i = 0; i < 32; i += 4){
            c0 = fmaf(__shfl_sync(FULL, ya, i+0), __ldg(g_w2b + (i+0)*32 + lane), c0);
            c1 = fmaf(__shfl_sync(FULL, ya, i+1), __ldg(g_w2b + (i+1)*32 + lane), c1);
            c2 = fmaf(__shfl_sync(FULL, ya, i+2), __ldg(g_w2b + (i+2)*32 + lane), c2);
            c3 = fmaf(__shfl_sync(FULL, ya, i+3), __ldg(g_w2b + (i+3)*32 + lane), c3);
        }
        float c = (c0 + c1) + (c2 + c3);
        c = fmaxf(c, 0.f);
        float mc = wsum(c) * 0.03125f;
        float dc = c - mc;
        float vc = wsum(dc*dc) * 0.03125f;
        float yb = dc * rsqrtf(vc + 1e-6f) * __ldg(g_g2b + lane) + __ldg(g_be2b + lane);
        float zf = yb + ya;   // residual

        float o0 = (lane < 13) ? __ldg(g_bout + lane) : 0.f;
        float o1 = 0.f;
        #pragma unroll
        for (int i = 0; i < 32; i += 2){
            float zi0 = __shfl_sync(FULL, zf, i);
            float zi1 = __shfl_sync(FULL, zf, i+1);
            if (lane < 13){
                o0 = fmaf(zi0, __ldg(g_wout + (i  )*13 + lane), o0);
                o1 = fmaf(zi1, __ldg(g_wout + (i+1)*13 + lane), o1);
            }
        }
        if (lane < 13) g_out[b*13 + lane] = tanhf(o0 + o1);
    }
}

extern "C" void kernel_launch(void* const* d_in, const int* in_sizes, int n_in,
                              void* d_out, int out_size)
{
    (void)in_sizes; (void)n_in; (void)out_size;
    const int SMEM_BYTES = (80*BSTR*2 + 128 + 8*32*ZS) * 4;   // ~101.9 KB
    cudaFuncSetAttribute(plane_kernel,
                         cudaFuncAttributeMaxDynamicSharedMemorySize, SMEM_BYTES);
    plane_kernel<<<1024, 256, SMEM_BYTES>>>(
        (const float*)d_in[0],  (const float*)d_in[1],  (const float*)d_in[2],
        (const float*)d_in[3],  (const int*)  d_in[4],  (const float*)d_in[5],
        (const float*)d_in[6],  (const float*)d_in[7],  (const float*)d_in[8],
        (const float*)d_in[9],  (const float*)d_in[10], (const float*)d_in[11],
        (const float*)d_in[12], (const float*)d_in[13], (const float*)d_in[14],
        (const float*)d_in[15], (const float*)d_in[16], (const float*)d_in[17],
        (const float*)d_in[18], (const float*)d_in[19],
        (float*)d_out);
}

// round 12
// speedup vs baseline: 1.4651x; 1.0009x over previous
#include <cuda_runtime.h>
#include <cuda_bf16.h>
#include <cstdint>

// PlaneModel: B=8192, NS=32, P=64, HID1=16, BASE=32, OUT=13, D_IN=79
// Layer-1 GEMV on mma.sync m16n8k16 bf16, hi/lo-pair split (K_eff=160), fp32 accum.
// warp = batch: 32 rows x 16 ch. A staged once as packed (hi,lo) words, ZS=84.
#define FULL 0xffffffffu
#define ZS 84        // word stride: frag reads (20*gr + j + c) mod 32 all-distinct -> conflict-free
#define BSTR 24      // B table stride: conflict-free frag reads

__device__ __forceinline__ uint32_t packsplit(float v){
    __nv_bfloat16 h = __float2bfloat16_rn(v);
    float hf = __bfloat162float(h);
    __nv_bfloat16 l = __float2bfloat16_rn(v - hf);
    uint16_t hu = *(uint16_t*)&h, lu = *(uint16_t*)&l;
    return (uint32_t)hu | ((uint32_t)lu << 16);      // low half = hi slot (element 2k)
}
__device__ __forceinline__ void mma16(float* d, const uint32_t* a, const uint32_t* b){
    asm volatile("mma.sync.aligned.m16n8k16.row.col.f32.bf16.bf16.f32 "
        "{%0,%1,%2,%3},{%4,%5,%6,%7},{%8,%9},{%0,%1,%2,%3};"
        : "+f"(d[0]), "+f"(d[1]), "+f"(d[2]), "+f"(d[3])
        : "r"(a[0]), "r"(a[1]), "r"(a[2]), "r"(a[3]), "r"(b[0]), "r"(b[1]));
}
__device__ __forceinline__ float wsum(float x){
    x += __shfl_xor_sync(FULL, x, 16);
    x += __shfl_xor_sync(FULL, x, 8);
    x += __shfl_xor_sync(FULL, x, 4);
    x += __shfl_xor_sync(FULL, x, 2);
    x += __shfl_xor_sync(FULL, x, 1);
    return x;
}

__global__ void __launch_bounds__(256)
plane_kernel(const float* __restrict__ g_pos,  const float* __restrict__ g_quat,
             const float* __restrict__ g_xz,   const float* __restrict__ g_aabb,
             const int*   __restrict__ g_widx, const float* __restrict__ g_pls,
             const float* __restrict__ g_w1,   const float* __restrict__ g_b1,
             const float* __restrict__ g_g1,   const float* __restrict__ g_be1,
             const float* __restrict__ g_w2a,  const float* __restrict__ g_b2a,
             const float* __restrict__ g_g2a,  const float* __restrict__ g_be2a,
             const float* __restrict__ g_w2b,  const float* __restrict__ g_b2b,
             const float* __restrict__ g_g2b,  const float* __restrict__ g_be2b,
             const float* __restrict__ g_wout, const float* __restrict__ g_bout,
             float* __restrict__ g_out)
{
    extern __shared__ __align__(16) uint32_t smw[];
    uint32_t* s_b1 = smw;               // 80*24 packed (bhi,bhi) [k][n]
    uint32_t* s_b2 = s_b1 + 80*BSTR;    // 80*24 packed (blo, 0 )
    float*    s_v  = (float*)(s_b2 + 80*BSTR);   // 8*16 per-warp layer-1 sums
    uint32_t* s_z  = (uint32_t*)(s_v + 128);     // 8 * 32*ZS packed A words

    const int tid  = threadIdx.x;
    const int warp = tid >> 5, lane = tid & 31;
    const int j    = lane & 3;          // thread in quad
    const int gr   = lane >> 2;         // group 0..7
    const int b    = (blockIdx.x << 3) + warp;
    uint32_t* szw = s_z + warp*(32*ZS);

    // ---- B tables (feature-permuted: xz 0..63, pick 64..66, pose 67..78, 79=0)
    for (int e = tid; e < 1280; e += 256){
        int k = e >> 4, n = e & 15;
        float w = 0.f;
        if (k < 79){
            int f = (k < 64) ? k + 3 : ((k < 67) ? k - 64 : k);
            w = __ldg(g_w1 + f*16 + n);
        }
        __nv_bfloat16 h = __float2bfloat16_rn(w);
        float hf = __bfloat162float(h);
        __nv_bfloat16 l = __float2bfloat16_rn(w - hf);
        uint16_t hu = *(uint16_t*)&h, lu = *(uint16_t*)&l;
        s_b1[k*BSTR + n] = (uint32_t)hu | ((uint32_t)hu << 16);  // pass1: hi*bhi + lo*bhi
        s_b2[k*BSTR + n] = (uint32_t)lu;                          // pass2: hi*blo
    }

    // ---- stage A: xz gather, pack hi/lo at staging time (hidden under LDG latency)
    const int idx = __ldg(g_widx + b*32 + lane);
    const float* xzb = g_xz + ((size_t)b << 15);
    #pragma unroll
    for (int r = 0; r < 32; r++){
        int ir = __shfl_sync(FULL, idx, r);
        const float* src = xzb + (ir << 6);
        szw[r*ZS + lane]      = packsplit(__ldcs(src + lane));
        szw[r*ZS + 32 + lane] = packsplit(__ldcs(src + 32 + lane));
    }

    // ---- pose features for this lane's sample -> words 64..79 (row = lane)
    {
        float qx = __ldg(g_quat + b*4 + 0), qy = __ldg(g_quat + b*4 + 1);
        float qz = __ldg(g_quat + b*4 + 2), qw = __ldg(g_quat + b*4 + 3);
        float rn = rsqrtf(qx*qx + qy*qy + qz*qz + qw*qw);
        qx *= rn; qy *= rn; qz *= rn; qw *= rn;
        float r00 = 1.f - 2.f*(qy*qy + qz*qz), r01 = 2.f*(qx*qy - qz*qw), r02 = 2.f*(qx*qz + qy*qw);
        float r10 = 2.f*(qx*qy + qz*qw), r11 = 1.f - 2.f*(qx*qx + qz*qz), r12 = 2.f*(qy*qz - qx*qw);
        float r20 = 2.f*(qx*qz - qy*qw), r21 = 2.f*(qy*qz + qx*qw), r22 = 1.f - 2.f*(qx*qx + qy*qy);
        float px = __ldg(g_pos + b*3 + 0), py = __ldg(g_pos + b*3 + 1), pz = __ldg(g_pos + b*3 + 2);
        float lox = __ldg(g_aabb + b*6 + 0), loy = __ldg(g_aabb + b*6 + 1), loz = __ldg(g_aabb + b*6 + 2);
        float hix = __ldg(g_aabb + b*6 + 3), hiy = __ldg(g_aabb + b*6 + 4), hiz = __ldg(g_aabb + b*6 + 5);
        float ci = (float)(idx >> 6) + 0.5f, cj = (float)((idx >> 3) & 7) + 0.5f, ck = (float)(idx & 7) + 0.5f;
        float vx = (ci*0.125f)*(hix - lox) + lox;
        float vy = (cj*0.125f)*(hiy - loy) + loy;
        float vz = (ck*0.125f)*(hiz - loz) + loz;
        float e = __expf(__ldg(g_pls));
        uint32_t* prow = szw + lane*ZS;
        prow[64] = packsplit(r00*vx + r01*vy + r02*vz + px);
        prow[65] = packsplit(r10*vx + r11*vy + r12*vz + py);
        prow[66] = packsplit(r20*vx + r21*vy + r22*vz + pz);
        prow[67] = packsplit(px*e); prow[68] = packsplit(py*e); prow[69] = packsplit(pz*e);
        prow[70] = packsplit(r00); prow[71] = packsplit(r01); prow[72] = packsplit(r02);
        prow[73] = packsplit(r10); prow[74] = packsplit(r11); prow[75] = packsplit(r12);
        prow[76] = packsplit(r20); prow[77] = packsplit(r21); prow[78] = packsplit(r22);
        prow[79] = 0u;
    }
    __syncthreads();

    // ---- bf16 MMA: 10 chunks x 2 mt x 2 nt x 2 passes = 80 MMAs, 8 chains of depth 10
    float dA[2][2][4], dB[2][2][4];
    #pragma unroll
    for (int mt = 0; mt < 2; mt++)
        #pragma unroll
        for (int nt = 0; nt < 2; nt++)
            #pragma unroll
            for (int q = 0; q < 4; q++){ dA[mt][nt][q] = 0.f; dB[mt][nt][q] = 0.f; }

    #pragma unroll
    for (int k0 = 0; k0 < 10; k0++){
        const int kA = k0*8 + j;
        uint32_t b1f[2][2], b2f[2][2];
        #pragma unroll
        for (int nt = 0; nt < 2; nt++){
            b1f[nt][0] = s_b1[(kA  )*BSTR + nt*8 + gr];
            b1f[nt][1] = s_b1[(kA+4)*BSTR + nt*8 + gr];
            b2f[nt][0] = s_b2[(kA  )*BSTR + nt*8 + gr];
            b2f[nt][1] = s_b2[(kA+4)*BSTR + nt*8 + gr];
        }
        #pragma unroll
        for (int mt = 0; mt < 2; mt++){
            const uint32_t* base = szw + (mt*16 + gr)*ZS + kA;
            uint32_t a[4] = { base[0], base[8*ZS], base[4], base[8*ZS + 4] };
            #pragma unroll
            for (int nt = 0; nt < 2; nt++){
                mma16(dA[mt][nt], a, b1f[nt]);
                mma16(dB[mt][nt], a, b2f[nt]);
            }
        }
    }

    float d[2][2][4];
    #pragma unroll
    for (int mt = 0; mt < 2; mt++)
        #pragma unroll
        for (int nt = 0; nt < 2; nt++)
            #pragma unroll
            for (int q = 0; q < 4; q++)
                d[mt][nt][q] = dA[mt][nt][q] + dB[mt][nt][q];

    // ---- epilogue: bias + relu + LN(16) per sample (quad shfl), x2, sum over samples ----
    float b1v[4] = { __ldg(g_b1 + 2*j),  __ldg(g_b1 + 2*j + 1),
                     __ldg(g_b1 + 8 + 2*j), __ldg(g_b1 + 9 + 2*j) };
    float g1v[4] = { __ldg(g_g1 + 2*j),  __ldg(g_g1 + 2*j + 1),
                     __ldg(g_g1 + 8 + 2*j), __ldg(g_g1 + 9 + 2*j) };
    float be1v[4] = { __ldg(g_be1 + 2*j), __ldg(g_be1 + 2*j + 1),
                      __ldg(g_be1 + 8 + 2*j), __ldg(g_be1 + 9 + 2*j) };

    float vsum[4] = {0.f, 0.f, 0.f, 0.f};
    #pragma unroll
    for (int mt = 0; mt < 2; mt++){
        #pragma unroll
        for (int rl = 0; rl < 2; rl++){
            float y0 = fmaxf(d[mt][0][rl*2]   + b1v[0], 0.f);
            float y1 = fmaxf(d[mt][0][rl*2+1] + b1v[1], 0.f);
            float y2 = fmaxf(d[mt][1][rl*2]   + b1v[2], 0.f);
            float y3 = fmaxf(d[mt][1][rl*2+1] + b1v[3], 0.f);
            float s = (y0 + y1) + (y2 + y3);
            s += __shfl_xor_sync(FULL, s, 1);
            s += __shfl_xor_sync(FULL, s, 2);
            float m = s * 0.0625f;
            float q0 = y0 - m, q1 = y1 - m, q2 = y2 - m, q3 = y3 - m;
            float q = (q0*q0 + q1*q1) + (q2*q2 + q3*q3);
            q += __shfl_xor_sync(FULL, q, 1);
            q += __shfl_xor_sync(FULL, q, 2);
            float is2 = 2.f * rsqrtf(q * 0.0625f + 1e-6f);   // LN then z+z
            vsum[0] += q0 * is2 * g1v[0] + 2.f*be1v[0];
            vsum[1] += q1 * is2 * g1v[1] + 2.f*be1v[1];
            vsum[2] += q2 * is2 * g1v[2] + 2.f*be1v[2];
            vsum[3] += q3 * is2 * g1v[3] + 2.f*be1v[3];
        }
    }
    #pragma unroll
    for (int c = 0; c < 4; c++){
        vsum[c] += __shfl_xor_sync(FULL, vsum[c], 4);
        vsum[c] += __shfl_xor_sync(FULL, vsum[c], 8);
        vsum[c] += __shfl_xor_sync(FULL, vsum[c], 16);
    }
    if (gr == 0){
        float* sv = s_v + warp*16;
        sv[2*j]     = vsum[0];
        sv[2*j + 1] = vsum[1];
        sv[8 + 2*j] = vsum[2];
        sv[9 + 2*j] = vsum[3];
    }
    __syncwarp(FULL);
    float v[16];
    #pragma unroll
    for (int t = 0; t < 4; t++){
        float4 s4 = *(const float4*)(s_v + warp*16 + 4*t);
        v[4*t] = s4.x; v[4*t+1] = s4.y; v[4*t+2] = s4.z; v[4*t+3] = s4.w;
    }

    // ---- head: lane = channel ----
    {
        float a0 = __ldg(g_b2a + lane), a1 = 0.f, a2 = 0.f, a3 = 0.f;
        #pragma unroll
        for (int i = 0; i < 16; i += 4){
            a0 = fmaf(v[i+0], __ldg(g_w2a + (i+0)*32 + lane), a0);
            a1 = fmaf(v[i+1], __ldg(g_w2a + (i+1)*32 + lane), a1);
            a2 = fmaf(v[i+2], __ldg(g_w2a + (i+2)*32 + lane), a2);
            a3 = fmaf(v[i+3], __ldg(g_w2a + (i+3)*32 + lane), a3);
        }
        float a = (a0 + a1) + (a2 + a3);
        a = fmaxf(a, 0.f);
        float ma = wsum(a) * 0.03125f;
        float da = a - ma;
        float va = wsum(da*da) * 0.03125f;
        float ya = da * rsqrtf(va + 1e-6f) * __ldg(g_g2a + lane) + __ldg(g_be2a + lane);

        float c0 = __ldg(g_b2b + lane), c1 = 0.f, c2 = 0.f, c3 = 0.f;
        #pragma unroll
        for (int i = 0; i < 32; i += 4){
            c0 = fmaf(__shfl_sync(FULL, ya, i+0), __ldg(g_w2b + (i+0)*32 + lane), c0);
            c1 = fmaf(__shfl_sync(FULL, ya, i+1), __ldg(g_w2b + (i+1)*32 + lane), c1);
            c2 = fmaf(__shfl_sync(FULL, ya, i+2), __ldg(g_w2b + (i+2)*32 + lane), c2);
            c3 = fmaf(__shfl_sync(FULL, ya, i+3), __ldg(g_w2b + (i+3)*32 + lane), c3);
        }
        float c = (c0 + c1) + (c2 + c3);
        c = fmaxf(c, 0.f);
        float mc = wsum(c) * 0.03125f;
        float dc = c - mc;
        float vc = wsum(dc*dc) * 0.03125f;
        float yb = dc * rsqrtf(vc + 1e-6f) * __ldg(g_g2b + lane) + __ldg(g_be2b + lane);
        float zf = yb + ya;   // residual

        float o0 = (lane < 13) ? __ldg(g_bout + lane) : 0.f;
        float o1 = 0.f;
        #pragma unroll
        for (int i = 0; i < 32; i += 2){
            float zi0 = __shfl_sync(FULL, zf, i);
            float zi1 = __shfl_sync(FULL, zf, i+1);
            if (lane < 13){
                o0 = fmaf(zi0, __ldg(g_wout + (i  )*13 + lane), o0);
                o1 = fmaf(zi1, __ldg(g_wout + (i+1)*13 + lane), o1);
            }
        }
        if (lane < 13) g_out[b*13 + lane] = tanhf(o0 + o1);
    }
}

extern "C" void kernel_launch(void* const* d_in, const int* in_sizes, int n_in,
                              void* d_out, int out_size)
{
    (void)in_sizes; (void)n_in; (void)out_size;
    const int SMEM_BYTES = (80*BSTR*2 + 128 + 8*32*ZS) * 4;   // ~101.9 KB
    cudaFuncSetAttribute(plane_kernel,
                         cudaFuncAttributeMaxDynamicSharedMemorySize, SMEM_BYTES);
    plane_kernel<<<1024, 256, SMEM_BYTES>>>(
        (const float*)d_in[0],  (const float*)d_in[1],  (const float*)d_in[2],
        (const float*)d_in[3],  (const int*)  d_in[4],  (const float*)d_in[5],
        (const float*)d_in[6],  (const float*)d_in[7],  (const float*)d_in[8],
        (const float*)d_in[9],  (const float*)d_in[10], (const float*)d_in[11],
        (const float*)d_in[12], (const float*)d_in[13], (const float*)d_in[14],
        (const float*)d_in[15], (const float*)d_in[16], (const float*)d_in[17],
        (const float*)d_in[18], (const float*)d_in[19],
        (float*)d_out);
}